// round 1
// baseline (speedup 1.0000x reference)
#include <cuda_runtime.h>

#define NS 65536
#define D  32
#define R  128

// Precomputed, transposed coefficient tables: [d][r] layout for conflict-free
// per-rule float4 loads from shared memory.
__device__ float gW[D * R];     // 1/(sqrt(2)*clamp(b,1e-8))
__device__ float gV[D * R];     // w * a
__device__ float gC[D * R];     // c[r][d] transposed
__device__ float gBias[R];      // c[r][D]

__global__ void anfis_precomp(const float* __restrict__ a,
                              const float* __restrict__ b,
                              const float* __restrict__ c) {
    int r = blockIdx.x;   // 128 blocks
    int d = threadIdx.x;  // 32 threads
    float av = a[r * D + d];
    float bv = fmaxf(b[r * D + d], 1e-8f);
    float w  = 0.70710678118654752f / bv;   // 1/(sqrt(2)*b)
    gW[d * R + r] = w;
    gV[d * R + r] = w * av;
    gC[d * R + r] = c[r * (D + 1) + d];
    if (d == 0) gBias[r] = c[r * (D + 1) + D];
}

__global__ void __launch_bounds__(256)
anfis_main(const float* __restrict__ X,
           float* __restrict__ pred,
           float* __restrict__ strengths,
           float* __restrict__ normalized) {
    // 3 * 16KB = 48KB static shared (exactly at the static limit)
    __shared__ float sW[D * R];
    __shared__ float sV[D * R];
    __shared__ float sC[D * R];
    __shared__ float sB[R];

    for (int i = threadIdx.x; i < D * R; i += blockDim.x) {
        sW[i] = gW[i];
        sV[i] = gV[i];
        sC[i] = gC[i];
    }
    if (threadIdx.x < R) sB[threadIdx.x] = gBias[threadIdx.x];
    __syncthreads();

    const int lane   = threadIdx.x & 31;
    const int warp   = (blockIdx.x * blockDim.x + threadIdx.x) >> 5;
    const int nwarps = (gridDim.x * blockDim.x) >> 5;
    const int rb     = lane * 4;   // this lane's 4 contiguous rules

    const float4 bb = *reinterpret_cast<const float4*>(&sB[rb]);

    for (int n = warp; n < NS; n += nwarps) {
        // Every lane holds the full X row (warp-uniform addresses -> broadcast)
        float x[D];
        const float4* Xr = reinterpret_cast<const float4*>(X + n * D);
        #pragma unroll
        for (int i = 0; i < D / 4; i++) {
            float4 v = Xr[i];
            x[4 * i + 0] = v.x;
            x[4 * i + 1] = v.y;
            x[4 * i + 2] = v.z;
            x[4 * i + 3] = v.w;
        }

        float ag0 = 0.f, ag1 = 0.f, ag2 = 0.f, ag3 = 0.f;     // sum of u^2
        float al0 = bb.x, al1 = bb.y, al2 = bb.z, al3 = bb.w; // consequent

        #pragma unroll
        for (int d = 0; d < D; d++) {
            const float xv = x[d];
            const float4 w4 = *reinterpret_cast<const float4*>(&sW[d * R + rb]);
            const float4 v4 = *reinterpret_cast<const float4*>(&sV[d * R + rb]);
            const float4 c4 = *reinterpret_cast<const float4*>(&sC[d * R + rb]);

            float u0 = fmaf(w4.x, xv, -v4.x);
            float u1 = fmaf(w4.y, xv, -v4.y);
            float u2 = fmaf(w4.z, xv, -v4.z);
            float u3 = fmaf(w4.w, xv, -v4.w);
            ag0 = fmaf(u0, u0, ag0);
            ag1 = fmaf(u1, u1, ag1);
            ag2 = fmaf(u2, u2, ag2);
            ag3 = fmaf(u3, u3, ag3);
            al0 = fmaf(c4.x, xv, al0);
            al1 = fmaf(c4.y, xv, al1);
            al2 = fmaf(c4.z, xv, al2);
            al3 = fmaf(c4.w, xv, al3);
        }

        const float s0 = __expf(-ag0);
        const float s1 = __expf(-ag1);
        const float s2 = __expf(-ag2);
        const float s3 = __expf(-ag3);

        float ssum = (s0 + s1) + (s2 + s3);
        float sp   = s0 * al0 + s1 * al1 + s2 * al2 + s3 * al3;
        #pragma unroll
        for (int off = 16; off > 0; off >>= 1) {
            ssum += __shfl_xor_sync(0xffffffffu, ssum, off);
            sp   += __shfl_xor_sync(0xffffffffu, sp,   off);
        }
        const float inv = 1.0f / (ssum + 1e-8f);

        const int base = n * R + rb;
        *reinterpret_cast<float4*>(&strengths[base])  = make_float4(s0, s1, s2, s3);
        *reinterpret_cast<float4*>(&normalized[base]) =
            make_float4(s0 * inv, s1 * inv, s2 * inv, s3 * inv);
        if (lane == 0) pred[n] = sp * inv;
    }
}

extern "C" void kernel_launch(void* const* d_in, const int* in_sizes, int n_in,
                              void* d_out, int out_size) {
    const float* X = (const float*)d_in[0];  // [65536, 32]
    const float* a = (const float*)d_in[1];  // [128, 32]
    const float* b = (const float*)d_in[2];  // [128, 32]
    const float* c = (const float*)d_in[3];  // [128, 33]

    float* out        = (float*)d_out;
    float* pred       = out;                 // [N]
    float* strengths  = out + NS;            // [N, R]
    float* normalized = out + NS + NS * R;   // [N, R]

    anfis_precomp<<<R, D>>>(a, b, c);
    anfis_main<<<592, 256>>>(X, pred, strengths, normalized);
}

// round 2
// speedup vs baseline: 4.0552x; 4.0552x over previous
#include <cuda_runtime.h>
#include <cstdint>

#define NS 65536
#define D  32
#define R  128
#define S  8          // samples per warp-group
#define WPB 8         // warps per block (256 threads)

typedef unsigned long long ull;

// smem byte layout (dynamic):
//   sW   [D*R] floats @ 0
//   sV   [D*R] floats @ 16384     (stores -w*a, so u = fma(w,x,v))
//   sC   [D*R] floats @ 32768
//   sB   [R]   floats @ 49152
//   xt   [WPB][D][S] ull @ 49664  (x duplicated into both halves)
#define OFF_W  0
#define OFF_V  16384
#define OFF_C  32768
#define OFF_B  49152
#define OFF_X  49664
#define SMEM_BYTES (49664 + WPB * D * S * 8)

__device__ float gW[D * R];
__device__ float gV[D * R];
__device__ float gC[D * R];
__device__ float gBias[R];

__global__ void anfis_precomp(const float* __restrict__ a,
                              const float* __restrict__ b,
                              const float* __restrict__ c) {
    int r = blockIdx.x, d = threadIdx.x;
    float av = a[r * D + d];
    float bv = fmaxf(b[r * D + d], 1e-8f);
    float w  = 0.70710678118654752f / bv;
    gW[d * R + r] = w;
    gV[d * R + r] = -w * av;           // pre-negated
    gC[d * R + r] = c[r * (D + 1) + d];
    if (d == 0) gBias[r] = c[r * (D + 1) + D];
}

__device__ __forceinline__ ull fma2(ull a, ull b, ull c) {
    ull d;
    asm("fma.rn.f32x2 %0, %1, %2, %3;" : "=l"(d) : "l"(a), "l"(b), "l"(c));
    return d;
}
__device__ __forceinline__ void lds128(uint32_t addr, ull& lo, ull& hi) {
    asm volatile("ld.shared.v2.u64 {%0, %1}, [%2];" : "=l"(lo), "=l"(hi) : "r"(addr));
}
__device__ __forceinline__ ull lds64(uint32_t addr) {
    ull v;
    asm volatile("ld.shared.u64 %0, [%1];" : "=l"(v) : "r"(addr));
    return v;
}
__device__ __forceinline__ void sts64(uint32_t addr, float lo, float hi) {
    asm volatile("st.shared.v2.f32 [%0], {%1, %2};" :: "r"(addr), "f"(lo), "f"(hi));
}
__device__ __forceinline__ void unpack2(ull v, float& lo, float& hi) {
    asm("mov.b64 {%0, %1}, %2;" : "=f"(lo), "=f"(hi) : "l"(v));
}
__device__ __forceinline__ ull pack2(float lo, float hi) {
    ull v;
    asm("mov.b64 %0, {%1, %2};" : "=l"(v) : "f"(lo), "f"(hi));
    return v;
}

__global__ void __launch_bounds__(256, 2)
anfis_main(const float* __restrict__ X,
           float* __restrict__ pred,
           float* __restrict__ strengths,
           float* __restrict__ normalized) {
    extern __shared__ float smem[];
    uint32_t sbase;
    {
        uint64_t t;
        asm("cvta.to.shared.u64 %0, %1;" : "=l"(t) : "l"(smem));
        sbase = (uint32_t)t;
    }

    // cooperative fill of coefficient tables
    for (int i = threadIdx.x; i < D * R; i += blockDim.x) {
        smem[OFF_W / 4 + i] = gW[i];
        smem[OFF_V / 4 + i] = gV[i];
        smem[OFF_C / 4 + i] = gC[i];
    }
    if (threadIdx.x < R) smem[OFF_B / 4 + threadIdx.x] = gBias[threadIdx.x];
    __syncthreads();

    const int lane  = threadIdx.x & 31;
    const int warp  = threadIdx.x >> 5;
    const int rb    = lane * 4;                      // 4 contiguous rules
    const uint32_t wA = sbase + OFF_W + rb * 4;      // + d*512 inside loop
    const uint32_t vA = sbase + OFF_V + rb * 4;
    const uint32_t cA = sbase + OFF_C + rb * 4;
    const uint32_t xA = sbase + OFF_X + warp * (D * S * 8);

    ull bb01, bb23;
    lds128(sbase + OFF_B + rb * 4, bb01, bb23);

    const int gw  = blockIdx.x * WPB + warp;
    const int ngw = gridDim.x * WPB;

    for (int g = gw; g < NS / S; g += ngw) {
        const int n0 = g * S;

        // ---- stage 8 rows of X into per-warp smem, duplicated as (x,x) pairs
        // lane handles float4s j = lane and lane+32 of the 8x32 tile
        {
            #pragma unroll
            for (int half = 0; half < 2; half++) {
                int j   = lane + half * 32;      // 0..63
                int row = j >> 3;                // 0..7
                int seg = j & 7;                 // 0..7
                float4 v = *reinterpret_cast<const float4*>(X + (n0 + row) * D + seg * 4);
                uint32_t base = xA + ((seg * 4) * S + row) * 8;
                sts64(base + 0 * S * 8, v.x, v.x);
                sts64(base + 1 * S * 8, v.y, v.y);
                sts64(base + 2 * S * 8, v.z, v.z);
                sts64(base + 3 * S * 8, v.w, v.w);
            }
            __syncwarp();
        }

        // ---- accumulators: [sample][rule-pair], packed f32x2
        ull ag[S][2], al[S][2];
        #pragma unroll
        for (int s = 0; s < S; s++) {
            ag[s][0] = 0ull; ag[s][1] = 0ull;
            al[s][0] = bb01; al[s][1] = bb23;
        }

        #pragma unroll 4
        for (int d = 0; d < D; d++) {
            ull w01, w23, v01, v23, c01, c23;
            lds128(wA + d * (R * 4), w01, w23);
            lds128(vA + d * (R * 4), v01, v23);
            lds128(cA + d * (R * 4), c01, c23);
            #pragma unroll
            for (int s = 0; s < S; s++) {
                ull xx = lds64(xA + (d * S + s) * 8);   // broadcast
                ull u01 = fma2(w01, xx, v01);
                ull u23 = fma2(w23, xx, v23);
                ag[s][0] = fma2(u01, u01, ag[s][0]);
                ag[s][1] = fma2(u23, u23, ag[s][1]);
                al[s][0] = fma2(c01, xx, al[s][0]);
                al[s][1] = fma2(c23, xx, al[s][1]);
            }
        }

        // ---- epilogue per sample
        #pragma unroll
        for (int s = 0; s < S; s++) {
            float e0, e1, e2, e3, r0, r1, r2, r3;
            unpack2(ag[s][0], e0, e1);
            unpack2(ag[s][1], e2, e3);
            unpack2(al[s][0], r0, r1);
            unpack2(al[s][1], r2, r3);
            float s0 = __expf(-e0), s1 = __expf(-e1);
            float s2 = __expf(-e2), s3 = __expf(-e3);

            float ssum = (s0 + s1) + (s2 + s3);
            float sp   = s0 * r0 + s1 * r1 + s2 * r2 + s3 * r3;
            #pragma unroll
            for (int off = 16; off > 0; off >>= 1) {
                ssum += __shfl_xor_sync(0xffffffffu, ssum, off);
                sp   += __shfl_xor_sync(0xffffffffu, sp,   off);
            }
            const float inv = 1.0f / (ssum + 1e-8f);

            const int base = (n0 + s) * R + rb;
            *reinterpret_cast<float4*>(&strengths[base])  = make_float4(s0, s1, s2, s3);
            *reinterpret_cast<float4*>(&normalized[base]) =
                make_float4(s0 * inv, s1 * inv, s2 * inv, s3 * inv);
            if (lane == 0) pred[n0 + s] = sp * inv;
        }
    }
}

extern "C" void kernel_launch(void* const* d_in, const int* in_sizes, int n_in,
                              void* d_out, int out_size) {
    const float* X = (const float*)d_in[0];
    const float* a = (const float*)d_in[1];
    const float* b = (const float*)d_in[2];
    const float* c = (const float*)d_in[3];

    float* out        = (float*)d_out;
    float* pred       = out;
    float* strengths  = out + NS;
    float* normalized = out + NS + NS * R;

    static bool attr_set = false;
    if (!attr_set) {
        cudaFuncSetAttribute(anfis_main,
                             cudaFuncAttributeMaxDynamicSharedMemorySize,
                             SMEM_BYTES);
        attr_set = true;
    }

    anfis_precomp<<<R, D>>>(a, b, c);
    anfis_main<<<296, 256, SMEM_BYTES>>>(X, pred, strengths, normalized);
}